// round 12
// baseline (speedup 1.0000x reference)
#include <cuda_runtime.h>

#define Bsz 8
#define NU  8192
#define MK  2048
#define C1  256
#define C2  256
#define CIN 512
#define DD  256
#define KE  32

// ---------------- scratch (static device globals; allocation-free launch) ----
__device__ float g_kfT[Bsz * MK * C2];                 // known_feats transposed (B,M,C2)
__device__ int   g_idx[Bsz * NU * 3];
__device__ float g_wgt[Bsz * NU * 3];
__device__ float g_FT[(size_t)Bsz * NU * CIN];         // feats point-major (B,N,512)
__device__ float g_h1[(size_t)Bsz * DD * NU];          // conv1 out (B,256,N)
__device__ float g_h [(size_t)Bsz * DD * NU];          // conv2 out (B,256,N)
__device__ float g_A [(size_t)Bsz * NU * KE];          // soft assignment (B,N,32)
__device__ float g_Asum[Bsz * KE];
__device__ float g_E [Bsz * KE * DD];                  // relu'd encoding (B,32,256)
__device__ float g_normsq[Bsz];
__device__ float g_ctx[Bsz * DD];
__device__ float g_alpha1[256], g_beta1[256], g_alpha2[256], g_beta2[256], g_c2[KE];

// ---------------- K0: fold BN into per-channel scale/shift; codeword norms; zero accumulators
__global__ void k_params(const float* __restrict__ cb1, const float* __restrict__ g1,
                         const float* __restrict__ bb1, const float* __restrict__ m1,
                         const float* __restrict__ v1,
                         const float* __restrict__ cb2, const float* __restrict__ g2,
                         const float* __restrict__ bb2, const float* __restrict__ m2,
                         const float* __restrict__ v2,
                         const float* __restrict__ cw) {
    int t = threadIdx.x;
    if (t < 256) {
        float a1 = g1[t] * rsqrtf(v1[t] + 1e-5f);
        g_alpha1[t] = a1;
        g_beta1[t]  = a1 * (cb1[t] - m1[t]) + bb1[t];
        float a2 = g2[t] * rsqrtf(v2[t] + 1e-5f);
        g_alpha2[t] = a2;
        g_beta2[t]  = a2 * (cb2[t] - m2[t]) + bb2[t];
    }
    if (t < KE) {
        float s = 0.f;
        for (int d = 0; d < DD; d++) { float c = cw[t * DD + d]; s += c * c; }
        g_c2[t] = s;
    }
    if (t < Bsz * KE) g_Asum[t] = 0.f;
    if (t < Bsz)      g_normsq[t] = 0.f;
}

// ---------------- K1: transpose known_feats (B,C2,M) -> g_kfT (B,M,C2)
__global__ void k_transpose_kf(const float* __restrict__ kf) {
    __shared__ float tile[32][33];
    int b = blockIdx.z;
    const float* s = kf + (size_t)b * C2 * MK;
    float* d = g_kfT + (size_t)b * MK * C2;
    int m0 = blockIdx.x * 32, c0 = blockIdx.y * 32;
    int tx = threadIdx.x, ty = threadIdx.y;
#pragma unroll
    for (int j = 0; j < 32; j += 8)
        tile[ty + j][tx] = s[(size_t)(c0 + ty + j) * MK + m0 + tx];
    __syncthreads();
#pragma unroll
    for (int j = 0; j < 32; j += 8)
        d[(size_t)(m0 + ty + j) * C2 + c0 + tx] = tile[tx][ty + j];
}

// ---------------- K2: three_nn (top-3 smallest distances)
__global__ void __launch_bounds__(256) k_three_nn(const float* __restrict__ unk,
                                                  const float* __restrict__ kn) {
    __shared__ float kx[MK], ky[MK], kz[MK];
    int b = blockIdx.y;
    const float* kb = kn + (size_t)b * MK * 3;
    for (int i = threadIdx.x; i < MK; i += blockDim.x) {
        kx[i] = kb[i * 3 + 0];
        ky[i] = kb[i * 3 + 1];
        kz[i] = kb[i * 3 + 2];
    }
    __syncthreads();
    int n = blockIdx.x * blockDim.x + threadIdx.x;
    const float* u = unk + ((size_t)b * NU + n) * 3;
    float ux = u[0], uy = u[1], uz = u[2];
    float b0 = 1e30f, b1 = 1e30f, b2 = 1e30f;
    int i0 = 0, i1 = 0, i2 = 0;
    for (int m = 0; m < MK; m++) {
        float dx = ux - kx[m], dy = uy - ky[m], dz = uz - kz[m];
        float d2 = dx * dx + dy * dy + dz * dz;
        if (d2 < b2) {
            if (d2 < b1) {
                if (d2 < b0) { b2 = b1; i2 = i1; b1 = b0; i1 = i0; b0 = d2; i0 = m; }
                else         { b2 = b1; i2 = i1; b1 = d2; i1 = m; }
            } else           { b2 = d2; i2 = m; }
        }
    }
    float d0 = sqrtf(fmaxf(b0, 1e-12f));
    float d1 = sqrtf(fmaxf(b1, 1e-12f));
    float d2s = sqrtf(fmaxf(b2, 1e-12f));
    float r0 = 1.f / (d0 + 1e-8f), r1 = 1.f / (d1 + 1e-8f), r2 = 1.f / (d2s + 1e-8f);
    float rs = 1.f / (r0 + r1 + r2);
    size_t base = ((size_t)b * NU + n) * 3;
    g_idx[base + 0] = i0; g_idx[base + 1] = i1; g_idx[base + 2] = i2;
    g_wgt[base + 0] = r0 * rs; g_wgt[base + 1] = r1 * rs; g_wgt[base + 2] = r2 * rs;
}

// ---------------- K3a: three_interpolate -> first 256 channels of g_FT (point-major)
__global__ void __launch_bounds__(256) k_interp() {
    int b = blockIdx.y;
    int p = threadIdx.x >> 6;      // 4 points per block
    int c = threadIdx.x & 63;      // float4 channel index (64 * 4 = 256)
    int n = blockIdx.x * 4 + p;
    size_t ib = ((size_t)b * NU + n) * 3;
    int i0 = g_idx[ib + 0], i1 = g_idx[ib + 1], i2 = g_idx[ib + 2];
    float w0 = g_wgt[ib + 0], w1 = g_wgt[ib + 1], w2 = g_wgt[ib + 2];
    const float4* f0 = (const float4*)(g_kfT + ((size_t)b * MK + i0) * C2);
    const float4* f1 = (const float4*)(g_kfT + ((size_t)b * MK + i1) * C2);
    const float4* f2 = (const float4*)(g_kfT + ((size_t)b * MK + i2) * C2);
    float4* out = (float4*)(g_FT + ((size_t)b * NU + n) * CIN);
    float4 v0 = f0[c], v1 = f1[c], v2 = f2[c];
    float4 r;
    r.x = w0 * v0.x + w1 * v1.x + w2 * v2.x;
    r.y = w0 * v0.y + w1 * v1.y + w2 * v2.y;
    r.z = w0 * v0.z + w1 * v1.z + w2 * v2.z;
    r.w = w0 * v0.w + w1 * v1.w + w2 * v2.w;
    out[c] = r;
}

// ---------------- K3b: transpose unknow_feats (B,256,N) into g_FT[...,256:512]
__global__ void k_uf_to_FT(const float* __restrict__ uf) {
    __shared__ float tile[32][33];
    int b = blockIdx.z;
    const float* s = uf + (size_t)b * C1 * NU;
    float* d = g_FT + (size_t)b * NU * CIN;
    int n0 = blockIdx.x * 32, c0 = blockIdx.y * 32;
    int tx = threadIdx.x, ty = threadIdx.y;
#pragma unroll
    for (int j = 0; j < 32; j += 8)
        tile[ty + j][tx] = s[(size_t)(c0 + ty + j) * NU + n0 + tx];
    __syncthreads();
#pragma unroll
    for (int j = 0; j < 32; j += 8)
        d[(size_t)(n0 + ty + j) * CIN + C2 + c0 + tx] = tile[tx][ty + j];
}

// ---------------- K4/K5: fused conv + BN + ReLU GEMM
// LAYER 1: C = W1(256x512) * FT^T  (B operand (n,k) row-major, "NT"), out g_h1
// LAYER 2: C = W2(256x256) * h1    (B operand (k,n) row-major, "NN"), out g_h
template <int LAYER>
__global__ void __launch_bounds__(256) k_gemm(const float* __restrict__ Wm) {
    constexpr int Ktot = (LAYER == 1) ? 512 : 256;
    __shared__ float As[16][128];
    __shared__ float Bs[16][64];
    int b = blockIdx.z;
    const float* Bmat = (LAYER == 1) ? (g_FT + (size_t)b * NU * CIN)
                                     : (g_h1 + (size_t)b * DD * NU);
    float* Out = (LAYER == 1) ? (g_h1 + (size_t)b * DD * NU)
                              : (g_h + (size_t)b * DD * NU);
    const float* alpha = (LAYER == 1) ? g_alpha1 : g_alpha2;
    const float* beta  = (LAYER == 1) ? g_beta1  : g_beta2;

    int m0 = blockIdx.y * 128;
    int n0 = blockIdx.x * 64;
    int t = threadIdx.x;
    int tm = t >> 4;            // 0..15 -> 8 m-rows each
    int tn = t & 15;            // 0..15 -> 4 n-cols each
    int lr = t >> 2;            // 0..63
    int lk = (t & 3) * 4;       // 0,4,8,12

    float acc[8][4];
#pragma unroll
    for (int i = 0; i < 8; i++)
#pragma unroll
        for (int j = 0; j < 4; j++) acc[i][j] = 0.f;

    for (int k0 = 0; k0 < Ktot; k0 += 16) {
        // A tile 128x16 (k-contiguous rows)
#pragma unroll
        for (int h = 0; h < 2; h++) {
            int row = lr + 64 * h;
            float4 v = *(const float4*)(Wm + (size_t)(m0 + row) * Ktot + k0 + lk);
            As[lk + 0][row] = v.x; As[lk + 1][row] = v.y;
            As[lk + 2][row] = v.z; As[lk + 3][row] = v.w;
        }
        // B tile
        if (LAYER == 1) {  // NT: Bmat is (N, Ktot)
            float4 v = *(const float4*)(Bmat + (size_t)(n0 + lr) * Ktot + k0 + lk);
            Bs[lk + 0][lr] = v.x; Bs[lk + 1][lr] = v.y;
            Bs[lk + 2][lr] = v.z; Bs[lk + 3][lr] = v.w;
        } else {           // NN: Bmat is (Ktot, N)
            int kr = t >> 4;
            int nc = (t & 15) * 4;
            float4 v = *(const float4*)(Bmat + (size_t)(k0 + kr) * NU + n0 + nc);
            *(float4*)(&Bs[kr][nc]) = v;
        }
        __syncthreads();
#pragma unroll
        for (int kk = 0; kk < 16; kk++) {
            float4 a0 = *(const float4*)(&As[kk][tm * 8]);
            float4 a1 = *(const float4*)(&As[kk][tm * 8 + 4]);
            float4 b4 = *(const float4*)(&Bs[kk][tn * 4]);
            float av[8] = {a0.x, a0.y, a0.z, a0.w, a1.x, a1.y, a1.z, a1.w};
            float bv[4] = {b4.x, b4.y, b4.z, b4.w};
#pragma unroll
            for (int i = 0; i < 8; i++)
#pragma unroll
                for (int j = 0; j < 4; j++)
                    acc[i][j] = fmaf(av[i], bv[j], acc[i][j]);
        }
        __syncthreads();
    }
#pragma unroll
    for (int i = 0; i < 8; i++) {
        int o = m0 + tm * 8 + i;
        float s = alpha[o], sh = beta[o];
        float4 v;
        v.x = fmaxf(acc[i][0] * s + sh, 0.f);
        v.y = fmaxf(acc[i][1] * s + sh, 0.f);
        v.z = fmaxf(acc[i][2] * s + sh, 0.f);
        v.w = fmaxf(acc[i][3] * s + sh, 0.f);
        *(float4*)(Out + (size_t)o * NU + n0 + tn * 4) = v;
    }
}

// ---------------- K6: soft assignment A = softmax_k(scale_k * ||x - c_k||^2), plus Asum
__global__ void __launch_bounds__(256) k_assign(const float* __restrict__ cw,
                                                const float* __restrict__ scale) {
    __shared__ float cws[256 * 40];   // [d][k], row pad 40 (16B aligned rows)
    __shared__ float wsum[8][KE];
    int b = blockIdx.y;
    int t = threadIdx.x;
    int n = blockIdx.x * 256 + t;
    for (int e = t; e < KE * DD; e += 256) {
        int k = e >> 8, d = e & 255;
        cws[d * 40 + k] = cw[e];
    }
    __syncthreads();

    const float* hb = g_h + (size_t)b * DD * NU + n;
    float dot[KE];
#pragma unroll
    for (int k = 0; k < KE; k++) dot[k] = 0.f;
    float xn2 = 0.f;
#pragma unroll 4
    for (int d = 0; d < DD; d++) {
        float xv = hb[(size_t)d * NU];
        xn2 += xv * xv;
        const float4* row = (const float4*)(cws + d * 40);
#pragma unroll
        for (int k4 = 0; k4 < 8; k4++) {
            float4 c4 = row[k4];
            dot[k4 * 4 + 0] += xv * c4.x;
            dot[k4 * 4 + 1] += xv * c4.y;
            dot[k4 * 4 + 2] += xv * c4.z;
            dot[k4 * 4 + 3] += xv * c4.w;
        }
    }
    float sl[KE];
    float mx = -1e30f;
#pragma unroll
    for (int k = 0; k < KE; k++) {
        sl[k] = scale[k] * (xn2 - 2.f * dot[k] + g_c2[k]);
        mx = fmaxf(mx, sl[k]);
    }
    float se = 0.f;
#pragma unroll
    for (int k = 0; k < KE; k++) { sl[k] = expf(sl[k] - mx); se += sl[k]; }
    float inv = 1.f / se;
#pragma unroll
    for (int k = 0; k < KE; k++) sl[k] *= inv;

    float* Ab = g_A + ((size_t)b * NU + n) * KE;
#pragma unroll
    for (int k = 0; k < KE; k += 4) {
        float4 v = {sl[k], sl[k + 1], sl[k + 2], sl[k + 3]};
        *(float4*)(Ab + k) = v;
    }
    // block-level Asum reduction
    int lane = t & 31, w = t >> 5;
#pragma unroll
    for (int k = 0; k < KE; k++) {
        float v = sl[k];
        v += __shfl_xor_sync(0xffffffff, v, 16);
        v += __shfl_xor_sync(0xffffffff, v, 8);
        v += __shfl_xor_sync(0xffffffff, v, 4);
        v += __shfl_xor_sync(0xffffffff, v, 2);
        v += __shfl_xor_sync(0xffffffff, v, 1);
        if (lane == 0) wsum[w][k] = v;
    }
    __syncthreads();
    if (t < KE) {
        float s = 0.f;
#pragma unroll
        for (int w2 = 0; w2 < 8; w2++) s += wsum[w2][t];
        atomicAdd(&g_Asum[b * KE + t], s);
    }
}

// ---------------- K7: E[b,k,d] = sum_n A[b,n,k]*h[b,d,n] - Asum*cw, relu, accumulate ||E||^2
__global__ void __launch_bounds__(256) k_egemm(const float* __restrict__ cw) {
    __shared__ float hs[64][64];
    __shared__ float As_[64][KE];
    __shared__ float red[256];
    int b = blockIdx.y;
    int d0 = blockIdx.x * 64;
    int t = threadIdx.x;
    int kq = t & 7;     // k = kq*4 .. +3
    int dq = t >> 3;    // d = d0 + dq*2 .. +1
    float acc[2][4] = {};
    const float* hb = g_h + (size_t)b * DD * NU;
    const float* Ab = g_A + (size_t)b * NU * KE;

    for (int n0 = 0; n0 < NU; n0 += 64) {
#pragma unroll
        for (int r = 0; r < 16; r++) {
            int e = r * 256 + t;
            int dd = e >> 6, nn = e & 63;
            hs[dd][nn] = hb[(size_t)(d0 + dd) * NU + n0 + nn];
        }
#pragma unroll
        for (int r = 0; r < 8; r++) {
            int e = r * 256 + t;
            As_[e >> 5][e & 31] = Ab[(size_t)n0 * KE + e];
        }
        __syncthreads();
#pragma unroll 4
        for (int nn = 0; nn < 64; nn++) {
            float h0 = hs[dq * 2 + 0][nn];
            float h1 = hs[dq * 2 + 1][nn];
            float a0 = As_[nn][kq * 4 + 0];
            float a1 = As_[nn][kq * 4 + 1];
            float a2 = As_[nn][kq * 4 + 2];
            float a3 = As_[nn][kq * 4 + 3];
            acc[0][0] += h0 * a0; acc[0][1] += h0 * a1;
            acc[0][2] += h0 * a2; acc[0][3] += h0 * a3;
            acc[1][0] += h1 * a0; acc[1][1] += h1 * a1;
            acc[1][2] += h1 * a2; acc[1][3] += h1 * a3;
        }
        __syncthreads();
    }
    float lsum = 0.f;
#pragma unroll
    for (int i = 0; i < 2; i++) {
        int d = d0 + dq * 2 + i;
#pragma unroll
        for (int j = 0; j < 4; j++) {
            int k = kq * 4 + j;
            float e = acc[i][j] - g_Asum[b * KE + k] * cw[k * DD + d];
            e = fmaxf(e, 0.f);
            g_E[((size_t)b * KE + k) * DD + d] = e;
            lsum += e * e;
        }
    }
    red[t] = lsum;
    __syncthreads();
    for (int s = 128; s > 0; s >>= 1) {
        if (t < s) red[t] += red[t + s];
        __syncthreads();
    }
    if (t == 0) atomicAdd(&g_normsq[b], red[0]);
}

// ---------------- K8: ctx[b,j] = sigmoid(dot(E_normalized[b], lin_w[j]) + lin_b[j])
__global__ void __launch_bounds__(256) k_ctx(const float* __restrict__ lw,
                                             const float* __restrict__ lb) {
    __shared__ float red[256];
    int b = blockIdx.y, j = blockIdx.x, t = threadIdx.x;
    const float4* e = (const float4*)(g_E + (size_t)b * KE * DD);
    const float4* w = (const float4*)(lw + (size_t)j * KE * DD);
    float s = 0.f;
#pragma unroll
    for (int i = 0; i < 8; i++) {
        int p = t + i * 256;
        float4 ev = e[p], wv = w[p];
        s += ev.x * wv.x + ev.y * wv.y + ev.z * wv.z + ev.w * wv.w;
    }
    red[t] = s;
    __syncthreads();
    for (int st = 128; st > 0; st >>= 1) {
        if (t < st) red[t] += red[t + st];
        __syncthreads();
    }
    if (t == 0) {
        float norm = fmaxf(sqrtf(g_normsq[b]), 1e-12f);
        float v = red[0] / norm + lb[j];
        g_ctx[b * DD + j] = 1.f / (1.f + expf(-v));
    }
}

// ---------------- K9: out[b,d,n] = h[b,d,n] * ctx[b,d]
__global__ void __launch_bounds__(256) k_out(float* __restrict__ out) {
    size_t i = (size_t)blockIdx.x * 256 + threadIdx.x;  // float4 index
    float4 h4 = ((const float4*)g_h)[i];
    size_t fi = i * 4;
    int d = (int)((fi >> 13) & 255);
    int b = (int)(fi >> 21);
    float c = g_ctx[b * DD + d];
    float4 v = {h4.x * c, h4.y * c, h4.z * c, h4.w * c};
    ((float4*)out)[i] = v;
}

// ---------------- launch --------------------------------------------------
extern "C" void kernel_launch(void* const* d_in, const int* in_sizes, int n_in,
                              void* d_out, int out_size) {
    const float* unknown = (const float*)d_in[0];
    const float* known   = (const float*)d_in[1];
    const float* uf      = (const float*)d_in[2];
    const float* kf      = (const float*)d_in[3];
    const float* w1      = (const float*)d_in[4];
    const float* cb1     = (const float*)d_in[5];
    const float* bg1     = (const float*)d_in[6];
    const float* bb1     = (const float*)d_in[7];
    const float* bm1     = (const float*)d_in[8];
    const float* bv1     = (const float*)d_in[9];
    const float* w2      = (const float*)d_in[10];
    const float* cb2     = (const float*)d_in[11];
    const float* bg2     = (const float*)d_in[12];
    const float* bb2     = (const float*)d_in[13];
    const float* bm2     = (const float*)d_in[14];
    const float* bv2     = (const float*)d_in[15];
    const float* cw      = (const float*)d_in[16];
    const float* esc     = (const float*)d_in[17];
    const float* lw      = (const float*)d_in[18];
    const float* lb      = (const float*)d_in[19];
    float* out = (float*)d_out;

    k_params<<<1, 256>>>(cb1, bg1, bb1, bm1, bv1, cb2, bg2, bb2, bm2, bv2, cw);
    k_transpose_kf<<<dim3(MK / 32, C2 / 32, Bsz), dim3(32, 8)>>>(kf);
    k_three_nn<<<dim3(NU / 256, Bsz), 256>>>(unknown, known);
    k_interp<<<dim3(NU / 4, Bsz), 256>>>();
    k_uf_to_FT<<<dim3(NU / 32, C1 / 32, Bsz), dim3(32, 8)>>>(uf);
    k_gemm<1><<<dim3(NU / 64, 2, Bsz), 256>>>(w1);
    k_gemm<2><<<dim3(NU / 64, 2, Bsz), 256>>>(w2);
    k_assign<<<dim3(NU / 256, Bsz), 256>>>(cw, esc);
    k_egemm<<<dim3(DD / 64, Bsz), 256>>>(cw);
    k_ctx<<<dim3(DD, Bsz), 256>>>(lw, lb);
    k_out<<<(Bsz * DD * NU) / 4 / 256, 256>>>(out);
}

// round 15
// speedup vs baseline: 1.0157x; 1.0157x over previous
#include <cuda_runtime.h>

#define Bsz 8
#define NU  8192
#define MK  2048
#define C1  256
#define C2  256
#define CIN 512
#define DD  256
#define KE  32

// ---------------- scratch (static device globals; allocation-free launch) ----
__device__ float g_kfT[Bsz * MK * C2];                 // known_feats transposed (B,M,C2)
__device__ int   g_idx[Bsz * NU * 3];
__device__ float g_wgt[Bsz * NU * 3];
__device__ float g_FT[(size_t)Bsz * NU * CIN];         // feats point-major (B,N,512)
__device__ float g_h1[(size_t)Bsz * DD * NU];          // conv1 out (B,256,N)
__device__ float g_h [(size_t)Bsz * DD * NU];          // conv2 out (B,256,N)
__device__ float g_A [(size_t)Bsz * NU * KE];          // soft assignment (B,N,32)
__device__ float g_Asum[Bsz * KE];
__device__ float g_E [Bsz * KE * DD];                  // relu'd encoding (B,32,256)
__device__ float g_normsq[Bsz];
__device__ float g_ctx[Bsz * DD];
__device__ float g_alpha1[256], g_beta1[256], g_alpha2[256], g_beta2[256], g_c2[KE];

// ---------------- K0: fold BN into per-channel scale/shift; codeword norms; zero accumulators
__global__ void k_params(const float* __restrict__ cb1, const float* __restrict__ g1,
                         const float* __restrict__ bb1, const float* __restrict__ m1,
                         const float* __restrict__ v1,
                         const float* __restrict__ cb2, const float* __restrict__ g2,
                         const float* __restrict__ bb2, const float* __restrict__ m2,
                         const float* __restrict__ v2,
                         const float* __restrict__ cw) {
    int t = threadIdx.x;
    if (t < 256) {
        float a1 = g1[t] * rsqrtf(v1[t] + 1e-5f);
        g_alpha1[t] = a1;
        g_beta1[t]  = a1 * (cb1[t] - m1[t]) + bb1[t];
        float a2 = g2[t] * rsqrtf(v2[t] + 1e-5f);
        g_alpha2[t] = a2;
        g_beta2[t]  = a2 * (cb2[t] - m2[t]) + bb2[t];
    }
    if (t < KE) {
        float s = 0.f;
        for (int d = 0; d < DD; d++) { float c = cw[t * DD + d]; s += c * c; }
        g_c2[t] = s;
    }
    if (t < Bsz * KE) g_Asum[t] = 0.f;
    if (t < Bsz)      g_normsq[t] = 0.f;
}

// ---------------- K1: transpose known_feats (B,C2,M) -> g_kfT (B,M,C2)
__global__ void k_transpose_kf(const float* __restrict__ kf) {
    __shared__ float tile[32][33];
    int b = blockIdx.z;
    const float* s = kf + (size_t)b * C2 * MK;
    float* d = g_kfT + (size_t)b * MK * C2;
    int m0 = blockIdx.x * 32, c0 = blockIdx.y * 32;
    int tx = threadIdx.x, ty = threadIdx.y;
#pragma unroll
    for (int j = 0; j < 32; j += 8)
        tile[ty + j][tx] = s[(size_t)(c0 + ty + j) * MK + m0 + tx];
    __syncthreads();
#pragma unroll
    for (int j = 0; j < 32; j += 8)
        d[(size_t)(m0 + ty + j) * C2 + c0 + tx] = tile[tx][ty + j];
}

// ---------------- K2: three_nn (top-3 smallest distances)
__global__ void __launch_bounds__(256) k_three_nn(const float* __restrict__ unk,
                                                  const float* __restrict__ kn) {
    __shared__ float kx[MK], ky[MK], kz[MK];
    int b = blockIdx.y;
    const float* kb = kn + (size_t)b * MK * 3;
    for (int i = threadIdx.x; i < MK; i += blockDim.x) {
        kx[i] = kb[i * 3 + 0];
        ky[i] = kb[i * 3 + 1];
        kz[i] = kb[i * 3 + 2];
    }
    __syncthreads();
    int n = blockIdx.x * blockDim.x + threadIdx.x;
    const float* u = unk + ((size_t)b * NU + n) * 3;
    float ux = u[0], uy = u[1], uz = u[2];
    float b0 = 1e30f, b1 = 1e30f, b2 = 1e30f;
    int i0 = 0, i1 = 0, i2 = 0;
    for (int m = 0; m < MK; m++) {
        float dx = ux - kx[m], dy = uy - ky[m], dz = uz - kz[m];
        float d2 = dx * dx + dy * dy + dz * dz;
        if (d2 < b2) {
            if (d2 < b1) {
                if (d2 < b0) { b2 = b1; i2 = i1; b1 = b0; i1 = i0; b0 = d2; i0 = m; }
                else         { b2 = b1; i2 = i1; b1 = d2; i1 = m; }
            } else           { b2 = d2; i2 = m; }
        }
    }
    float d0 = sqrtf(fmaxf(b0, 1e-12f));
    float d1 = sqrtf(fmaxf(b1, 1e-12f));
    float d2s = sqrtf(fmaxf(b2, 1e-12f));
    float r0 = 1.f / (d0 + 1e-8f), r1 = 1.f / (d1 + 1e-8f), r2 = 1.f / (d2s + 1e-8f);
    float rs = 1.f / (r0 + r1 + r2);
    size_t base = ((size_t)b * NU + n) * 3;
    g_idx[base + 0] = i0; g_idx[base + 1] = i1; g_idx[base + 2] = i2;
    g_wgt[base + 0] = r0 * rs; g_wgt[base + 1] = r1 * rs; g_wgt[base + 2] = r2 * rs;
}

// ---------------- K3a: three_interpolate -> first 256 channels of g_FT (point-major)
__global__ void __launch_bounds__(256) k_interp() {
    int b = blockIdx.y;
    int p = threadIdx.x >> 6;      // 4 points per block
    int c = threadIdx.x & 63;      // float4 channel index (64 * 4 = 256)
    int n = blockIdx.x * 4 + p;
    size_t ib = ((size_t)b * NU + n) * 3;
    int i0 = g_idx[ib + 0], i1 = g_idx[ib + 1], i2 = g_idx[ib + 2];
    float w0 = g_wgt[ib + 0], w1 = g_wgt[ib + 1], w2 = g_wgt[ib + 2];
    const float4* f0 = (const float4*)(g_kfT + ((size_t)b * MK + i0) * C2);
    const float4* f1 = (const float4*)(g_kfT + ((size_t)b * MK + i1) * C2);
    const float4* f2 = (const float4*)(g_kfT + ((size_t)b * MK + i2) * C2);
    float4* out = (float4*)(g_FT + ((size_t)b * NU + n) * CIN);
    float4 v0 = f0[c], v1 = f1[c], v2 = f2[c];
    float4 r;
    r.x = w0 * v0.x + w1 * v1.x + w2 * v2.x;
    r.y = w0 * v0.y + w1 * v1.y + w2 * v2.y;
    r.z = w0 * v0.z + w1 * v1.z + w2 * v2.z;
    r.w = w0 * v0.w + w1 * v1.w + w2 * v2.w;
    out[c] = r;
}

// ---------------- K3b: transpose unknow_feats (B,256,N) into g_FT[...,256:512]
__global__ void k_uf_to_FT(const float* __restrict__ uf) {
    __shared__ float tile[32][33];
    int b = blockIdx.z;
    const float* s = uf + (size_t)b * C1 * NU;
    float* d = g_FT + (size_t)b * NU * CIN;
    int n0 = blockIdx.x * 32, c0 = blockIdx.y * 32;
    int tx = threadIdx.x, ty = threadIdx.y;
#pragma unroll
    for (int j = 0; j < 32; j += 8)
        tile[ty + j][tx] = s[(size_t)(c0 + ty + j) * NU + n0 + tx];
    __syncthreads();
#pragma unroll
    for (int j = 0; j < 32; j += 8)
        d[(size_t)(n0 + ty + j) * CIN + C2 + c0 + tx] = tile[tx][ty + j];
}

// ---------------- K4/K5: fused conv + BN + ReLU GEMM
// LAYER 1: C = W1(256x512) * FT^T  (B operand (n,k) row-major, "NT"), out g_h1
// LAYER 2: C = W2(256x256) * h1    (B operand (k,n) row-major, "NN"), out g_h
template <int LAYER>
__global__ void __launch_bounds__(256) k_gemm(const float* __restrict__ Wm) {
    constexpr int Ktot = (LAYER == 1) ? 512 : 256;
    __shared__ float As[16][128];
    __shared__ float Bs[16][64];
    int b = blockIdx.z;
    const float* Bmat = (LAYER == 1) ? (g_FT + (size_t)b * NU * CIN)
                                     : (g_h1 + (size_t)b * DD * NU);
    float* Out = (LAYER == 1) ? (g_h1 + (size_t)b * DD * NU)
                              : (g_h + (size_t)b * DD * NU);
    const float* alpha = (LAYER == 1) ? g_alpha1 : g_alpha2;
    const float* beta  = (LAYER == 1) ? g_beta1  : g_beta2;

    int m0 = blockIdx.y * 128;
    int n0 = blockIdx.x * 64;
    int t = threadIdx.x;
    int tm = t >> 4;            // 0..15 -> 8 m-rows each
    int tn = t & 15;            // 0..15 -> 4 n-cols each
    int lr = t >> 2;            // 0..63
    int lk = (t & 3) * 4;       // 0,4,8,12

    float acc[8][4];
#pragma unroll
    for (int i = 0; i < 8; i++)
#pragma unroll
        for (int j = 0; j < 4; j++) acc[i][j] = 0.f;

    for (int k0 = 0; k0 < Ktot; k0 += 16) {
        // A tile 128x16 (k-contiguous rows)
#pragma unroll
        for (int h = 0; h < 2; h++) {
            int row = lr + 64 * h;
            float4 v = *(const float4*)(Wm + (size_t)(m0 + row) * Ktot + k0 + lk);
            As[lk + 0][row] = v.x; As[lk + 1][row] = v.y;
            As[lk + 2][row] = v.z; As[lk + 3][row] = v.w;
        }
        // B tile
        if (LAYER == 1) {  // NT: Bmat is (N, Ktot)
            float4 v = *(const float4*)(Bmat + (size_t)(n0 + lr) * Ktot + k0 + lk);
            Bs[lk + 0][lr] = v.x; Bs[lk + 1][lr] = v.y;
            Bs[lk + 2][lr] = v.z; Bs[lk + 3][lr] = v.w;
        } else {           // NN: Bmat is (Ktot, N)
            int kr = t >> 4;
            int nc = (t & 15) * 4;
            float4 v = *(const float4*)(Bmat + (size_t)(k0 + kr) * NU + n0 + nc);
            *(float4*)(&Bs[kr][nc]) = v;
        }
        __syncthreads();
#pragma unroll
        for (int kk = 0; kk < 16; kk++) {
            float4 a0 = *(const float4*)(&As[kk][tm * 8]);
            float4 a1 = *(const float4*)(&As[kk][tm * 8 + 4]);
            float4 b4 = *(const float4*)(&Bs[kk][tn * 4]);
            float av[8] = {a0.x, a0.y, a0.z, a0.w, a1.x, a1.y, a1.z, a1.w};
            float bv[4] = {b4.x, b4.y, b4.z, b4.w};
#pragma unroll
            for (int i = 0; i < 8; i++)
#pragma unroll
                for (int j = 0; j < 4; j++)
                    acc[i][j] = fmaf(av[i], bv[j], acc[i][j]);
        }
        __syncthreads();
    }
#pragma unroll
    for (int i = 0; i < 8; i++) {
        int o = m0 + tm * 8 + i;
        float s = alpha[o], sh = beta[o];
        float4 v;
        v.x = fmaxf(acc[i][0] * s + sh, 0.f);
        v.y = fmaxf(acc[i][1] * s + sh, 0.f);
        v.z = fmaxf(acc[i][2] * s + sh, 0.f);
        v.w = fmaxf(acc[i][3] * s + sh, 0.f);
        *(float4*)(Out + (size_t)o * NU + n0 + tn * 4) = v;
    }
}

// ---------------- K6: soft assignment A = softmax_k(scale_k * ||x - c_k||^2), plus Asum
__global__ void __launch_bounds__(256) k_assign(const float* __restrict__ cw,
                                                const float* __restrict__ scale) {
    __shared__ float cws[256 * 40];   // [d][k], row pad 40 (16B aligned rows)
    __shared__ float wsum[8][KE];
    int b = blockIdx.y;
    int t = threadIdx.x;
    int n = blockIdx.x * 256 + t;
    for (int e = t; e < KE * DD; e += 256) {
        int k = e >> 8, d = e & 255;
        cws[d * 40 + k] = cw[e];
    }
    __syncthreads();

    const float* hb = g_h + (size_t)b * DD * NU + n;
    float dot[KE];
#pragma unroll
    for (int k = 0; k < KE; k++) dot[k] = 0.f;
    float xn2 = 0.f;
#pragma unroll 4
    for (int d = 0; d < DD; d++) {
        float xv = hb[(size_t)d * NU];
        xn2 += xv * xv;
        const float4* row = (const float4*)(cws + d * 40);
#pragma unroll
        for (int k4 = 0; k4 < 8; k4++) {
            float4 c4 = row[k4];
            dot[k4 * 4 + 0] += xv * c4.x;
            dot[k4 * 4 + 1] += xv * c4.y;
            dot[k4 * 4 + 2] += xv * c4.z;
            dot[k4 * 4 + 3] += xv * c4.w;
        }
    }
    float sl[KE];
    float mx = -1e30f;
#pragma unroll
    for (int k = 0; k < KE; k++) {
        sl[k] = scale[k] * (xn2 - 2.f * dot[k] + g_c2[k]);
        mx = fmaxf(mx, sl[k]);
    }
    float se = 0.f;
#pragma unroll
    for (int k = 0; k < KE; k++) { sl[k] = expf(sl[k] - mx); se += sl[k]; }
    float inv = 1.f / se;
#pragma unroll
    for (int k = 0; k < KE; k++) sl[k] *= inv;

    float* Ab = g_A + ((size_t)b * NU + n) * KE;
#pragma unroll
    for (int k = 0; k < KE; k += 4) {
        float4 v = {sl[k], sl[k + 1], sl[k + 2], sl[k + 3]};
        *(float4*)(Ab + k) = v;
    }
    // block-level Asum reduction
    int lane = t & 31, w = t >> 5;
#pragma unroll
    for (int k = 0; k < KE; k++) {
        float v = sl[k];
        v += __shfl_xor_sync(0xffffffff, v, 16);
        v += __shfl_xor_sync(0xffffffff, v, 8);
        v += __shfl_xor_sync(0xffffffff, v, 4);
        v += __shfl_xor_sync(0xffffffff, v, 2);
        v += __shfl_xor_sync(0xffffffff, v, 1);
        if (lane == 0) wsum[w][k] = v;
    }
    __syncthreads();
    if (t < KE) {
        float s = 0.f;
#pragma unroll
        for (int w2 = 0; w2 < 8; w2++) s += wsum[w2][t];
        atomicAdd(&g_Asum[b * KE + t], s);
    }
}

// ---------------- K7: E[b,k,d] = sum_n A[b,n,k]*h[b,d,n] - Asum*cw, relu, accumulate ||E||^2
__global__ void __launch_bounds__(256) k_egemm(const float* __restrict__ cw) {
    __shared__ float hs[64][64];
    __shared__ float As_[64][KE];
    __shared__ float red[256];
    int b = blockIdx.y;
    int d0 = blockIdx.x * 64;
    int t = threadIdx.x;
    int kq = t & 7;     // k = kq*4 .. +3
    int dq = t >> 3;    // d = d0 + dq*2 .. +1
    float acc[2][4] = {};
    const float* hb = g_h + (size_t)b * DD * NU;
    const float* Ab = g_A + (size_t)b * NU * KE;

    for (int n0 = 0; n0 < NU; n0 += 64) {
#pragma unroll
        for (int r = 0; r < 16; r++) {
            int e = r * 256 + t;
            int dd = e >> 6, nn = e & 63;
            hs[dd][nn] = hb[(size_t)(d0 + dd) * NU + n0 + nn];
        }
#pragma unroll
        for (int r = 0; r < 8; r++) {
            int e = r * 256 + t;
            As_[e >> 5][e & 31] = Ab[(size_t)n0 * KE + e];
        }
        __syncthreads();
#pragma unroll 4
        for (int nn = 0; nn < 64; nn++) {
            float h0 = hs[dq * 2 + 0][nn];
            float h1 = hs[dq * 2 + 1][nn];
            float a0 = As_[nn][kq * 4 + 0];
            float a1 = As_[nn][kq * 4 + 1];
            float a2 = As_[nn][kq * 4 + 2];
            float a3 = As_[nn][kq * 4 + 3];
            acc[0][0] += h0 * a0; acc[0][1] += h0 * a1;
            acc[0][2] += h0 * a2; acc[0][3] += h0 * a3;
            acc[1][0] += h1 * a0; acc[1][1] += h1 * a1;
            acc[1][2] += h1 * a2; acc[1][3] += h1 * a3;
        }
        __syncthreads();
    }
    float lsum = 0.f;
#pragma unroll
    for (int i = 0; i < 2; i++) {
        int d = d0 + dq * 2 + i;
#pragma unroll
        for (int j = 0; j < 4; j++) {
            int k = kq * 4 + j;
            float e = acc[i][j] - g_Asum[b * KE + k] * cw[k * DD + d];
            e = fmaxf(e, 0.f);
            g_E[((size_t)b * KE + k) * DD + d] = e;
            lsum += e * e;
        }
    }
    red[t] = lsum;
    __syncthreads();
    for (int s = 128; s > 0; s >>= 1) {
        if (t < s) red[t] += red[t + s];
        __syncthreads();
    }
    if (t == 0) atomicAdd(&g_normsq[b], red[0]);
}

// ---------------- K8: ctx[b,j] = sigmoid(dot(E_normalized[b], lin_w[j]) + lin_b[j])
__global__ void __launch_bounds__(256) k_ctx(const float* __restrict__ lw,
                                             const float* __restrict__ lb) {
    __shared__ float red[256];
    int b = blockIdx.y, j = blockIdx.x, t = threadIdx.x;
    const float4* e = (const float4*)(g_E + (size_t)b * KE * DD);
    const float4* w = (const float4*)(lw + (size_t)j * KE * DD);
    float s = 0.f;
#pragma unroll
    for (int i = 0; i < 8; i++) {
        int p = t + i * 256;
        float4 ev = e[p], wv = w[p];
        s += ev.x * wv.x + ev.y * wv.y + ev.z * wv.z + ev.w * wv.w;
    }
    red[t] = s;
    __syncthreads();
    for (int st = 128; st > 0; st >>= 1) {
        if (t < st) red[t] += red[t + st];
        __syncthreads();
    }
    if (t == 0) {
        float norm = fmaxf(sqrtf(g_normsq[b]), 1e-12f);
        float v = red[0] / norm + lb[j];
        g_ctx[b * DD + j] = 1.f / (1.f + expf(-v));
    }
}

// ---------------- K9: out[b,d,n] = h[b,d,n] * ctx[b,d]
__global__ void __launch_bounds__(256) k_out(float* __restrict__ out) {
    size_t i = (size_t)blockIdx.x * 256 + threadIdx.x;  // float4 index
    float4 h4 = ((const float4*)g_h)[i];
    size_t fi = i * 4;
    int d = (int)((fi >> 13) & 255);
    int b = (int)(fi >> 21);
    float c = g_ctx[b * DD + d];
    float4 v = {h4.x * c, h4.y * c, h4.z * c, h4.w * c};
    ((float4*)out)[i] = v;
}

// ---------------- launch --------------------------------------------------
extern "C" void kernel_launch(void* const* d_in, const int* in_sizes, int n_in,
                              void* d_out, int out_size) {
    const float* unknown = (const float*)d_in[0];
    const float* known   = (const float*)d_in[1];
    const float* uf      = (const float*)d_in[2];
    const float* kf      = (const float*)d_in[3];
    const float* w1      = (const float*)d_in[4];
    const float* cb1     = (const float*)d_in[5];
    const float* bg1     = (const float*)d_in[6];
    const float* bb1     = (const float*)d_in[7];
    const float* bm1     = (const float*)d_in[8];
    const float* bv1     = (const float*)d_in[9];
    const float* w2      = (const float*)d_in[10];
    const float* cb2     = (const float*)d_in[11];
    const float* bg2     = (const float*)d_in[12];
    const float* bb2     = (const float*)d_in[13];
    const float* bm2     = (const float*)d_in[14];
    const float* bv2     = (const float*)d_in[15];
    const float* cw      = (const float*)d_in[16];
    const float* esc     = (const float*)d_in[17];
    const float* lw      = (const float*)d_in[18];
    const float* lb      = (const float*)d_in[19];
    float* out = (float*)d_out;

    k_params<<<1, 256>>>(cb1, bg1, bb1, bm1, bv1, cb2, bg2, bb2, bm2, bv2, cw);
    k_transpose_kf<<<dim3(MK / 32, C2 / 32, Bsz), dim3(32, 8)>>>(kf);
    k_three_nn<<<dim3(NU / 256, Bsz), 256>>>(unknown, known);
    k_interp<<<dim3(NU / 4, Bsz), 256>>>();
    k_uf_to_FT<<<dim3(NU / 32, C1 / 32, Bsz), dim3(32, 8)>>>(uf);
    k_gemm<1><<<dim3(NU / 64, 2, Bsz), 256>>>(w1);
    k_gemm<2><<<dim3(NU / 64, 2, Bsz), 256>>>(w2);
    k_assign<<<dim3(NU / 256, Bsz), 256>>>(cw, esc);
    k_egemm<<<dim3(DD / 64, Bsz), 256>>>(cw);
    k_ctx<<<dim3(DD, Bsz), 256>>>(lw, lb);
    k_out<<<(Bsz * DD * NU) / 4 / 256, 256>>>(out);
}

// round 16
// speedup vs baseline: 1.0188x; 1.0030x over previous
#include <cuda_runtime.h>

#define Bsz 8
#define NU  8192
#define MK  2048
#define C1  256
#define C2  256
#define CIN 512
#define DD  256
#define KE  32

// ---------------- scratch (static device globals; allocation-free launch) ----
__device__ float g_kfT[Bsz * MK * C2];                 // known_feats transposed (B,M,C2)
__device__ int   g_idx[Bsz * NU * 3];
__device__ float g_wgt[Bsz * NU * 3];
__device__ float g_FT[(size_t)Bsz * NU * CIN];         // feats point-major (B,N,512)
__device__ float g_h1[(size_t)Bsz * DD * NU];          // conv1 out (B,256,N)
__device__ float g_h [(size_t)Bsz * DD * NU];          // conv2 out (B,256,N)
__device__ float g_A [(size_t)Bsz * NU * KE];          // soft assignment (B,N,32)
__device__ float g_Asum[Bsz * KE];
__device__ float g_E [Bsz * KE * DD];                  // relu'd encoding (B,32,256)
__device__ float g_normsq[Bsz];
__device__ float g_ctx[Bsz * DD];
__device__ float g_alpha1[256], g_beta1[256], g_alpha2[256], g_beta2[256], g_c2[KE];

// ---------------- K0: fold BN into per-channel scale/shift; codeword norms; zero accumulators
__global__ void k_params(const float* __restrict__ cb1, const float* __restrict__ g1,
                         const float* __restrict__ bb1, const float* __restrict__ m1,
                         const float* __restrict__ v1,
                         const float* __restrict__ cb2, const float* __restrict__ g2,
                         const float* __restrict__ bb2, const float* __restrict__ m2,
                         const float* __restrict__ v2,
                         const float* __restrict__ cw) {
    int t = threadIdx.x;
    if (t < 256) {
        float a1 = g1[t] * rsqrtf(v1[t] + 1e-5f);
        g_alpha1[t] = a1;
        g_beta1[t]  = a1 * (cb1[t] - m1[t]) + bb1[t];
        float a2 = g2[t] * rsqrtf(v2[t] + 1e-5f);
        g_alpha2[t] = a2;
        g_beta2[t]  = a2 * (cb2[t] - m2[t]) + bb2[t];
    }
    if (t < KE) {
        float s = 0.f;
        for (int d = 0; d < DD; d++) { float c = cw[t * DD + d]; s += c * c; }
        g_c2[t] = s;
    }
    if (t < Bsz * KE) g_Asum[t] = 0.f;
    if (t < Bsz)      g_normsq[t] = 0.f;
}

// ---------------- K1: transpose known_feats (B,C2,M) -> g_kfT (B,M,C2)
__global__ void k_transpose_kf(const float* __restrict__ kf) {
    __shared__ float tile[32][33];
    int b = blockIdx.z;
    const float* s = kf + (size_t)b * C2 * MK;
    float* d = g_kfT + (size_t)b * MK * C2;
    int m0 = blockIdx.x * 32, c0 = blockIdx.y * 32;
    int tx = threadIdx.x, ty = threadIdx.y;
#pragma unroll
    for (int j = 0; j < 32; j += 8)
        tile[ty + j][tx] = s[(size_t)(c0 + ty + j) * MK + m0 + tx];
    __syncthreads();
#pragma unroll
    for (int j = 0; j < 32; j += 8)
        d[(size_t)(m0 + ty + j) * C2 + c0 + tx] = tile[tx][ty + j];
}

// ---------------- K2: three_nn (top-3 smallest distances)
__global__ void __launch_bounds__(256) k_three_nn(const float* __restrict__ unk,
                                                  const float* __restrict__ kn) {
    __shared__ float kx[MK], ky[MK], kz[MK];
    int b = blockIdx.y;
    const float* kb = kn + (size_t)b * MK * 3;
    for (int i = threadIdx.x; i < MK; i += blockDim.x) {
        kx[i] = kb[i * 3 + 0];
        ky[i] = kb[i * 3 + 1];
        kz[i] = kb[i * 3 + 2];
    }
    __syncthreads();
    int n = blockIdx.x * blockDim.x + threadIdx.x;
    const float* u = unk + ((size_t)b * NU + n) * 3;
    float ux = u[0], uy = u[1], uz = u[2];
    float b0 = 1e30f, b1 = 1e30f, b2 = 1e30f;
    int i0 = 0, i1 = 0, i2 = 0;
    for (int m = 0; m < MK; m++) {
        float dx = ux - kx[m], dy = uy - ky[m], dz = uz - kz[m];
        float d2 = dx * dx + dy * dy + dz * dz;
        if (d2 < b2) {
            if (d2 < b1) {
                if (d2 < b0) { b2 = b1; i2 = i1; b1 = b0; i1 = i0; b0 = d2; i0 = m; }
                else         { b2 = b1; i2 = i1; b1 = d2; i1 = m; }
            } else           { b2 = d2; i2 = m; }
        }
    }
    float d0 = sqrtf(fmaxf(b0, 1e-12f));
    float d1 = sqrtf(fmaxf(b1, 1e-12f));
    float d2s = sqrtf(fmaxf(b2, 1e-12f));
    float r0 = 1.f / (d0 + 1e-8f), r1 = 1.f / (d1 + 1e-8f), r2 = 1.f / (d2s + 1e-8f);
    float rs = 1.f / (r0 + r1 + r2);
    size_t base = ((size_t)b * NU + n) * 3;
    g_idx[base + 0] = i0; g_idx[base + 1] = i1; g_idx[base + 2] = i2;
    g_wgt[base + 0] = r0 * rs; g_wgt[base + 1] = r1 * rs; g_wgt[base + 2] = r2 * rs;
}

// ---------------- K3a: three_interpolate -> first 256 channels of g_FT (point-major)
__global__ void __launch_bounds__(256) k_interp() {
    int b = blockIdx.y;
    int p = threadIdx.x >> 6;      // 4 points per block
    int c = threadIdx.x & 63;      // float4 channel index (64 * 4 = 256)
    int n = blockIdx.x * 4 + p;
    size_t ib = ((size_t)b * NU + n) * 3;
    int i0 = g_idx[ib + 0], i1 = g_idx[ib + 1], i2 = g_idx[ib + 2];
    float w0 = g_wgt[ib + 0], w1 = g_wgt[ib + 1], w2 = g_wgt[ib + 2];
    const float4* f0 = (const float4*)(g_kfT + ((size_t)b * MK + i0) * C2);
    const float4* f1 = (const float4*)(g_kfT + ((size_t)b * MK + i1) * C2);
    const float4* f2 = (const float4*)(g_kfT + ((size_t)b * MK + i2) * C2);
    float4* out = (float4*)(g_FT + ((size_t)b * NU + n) * CIN);
    float4 v0 = f0[c], v1 = f1[c], v2 = f2[c];
    float4 r;
    r.x = w0 * v0.x + w1 * v1.x + w2 * v2.x;
    r.y = w0 * v0.y + w1 * v1.y + w2 * v2.y;
    r.z = w0 * v0.z + w1 * v1.z + w2 * v2.z;
    r.w = w0 * v0.w + w1 * v1.w + w2 * v2.w;
    out[c] = r;
}

// ---------------- K3b: transpose unknow_feats (B,256,N) into g_FT[...,256:512]
__global__ void k_uf_to_FT(const float* __restrict__ uf) {
    __shared__ float tile[32][33];
    int b = blockIdx.z;
    const float* s = uf + (size_t)b * C1 * NU;
    float* d = g_FT + (size_t)b * NU * CIN;
    int n0 = blockIdx.x * 32, c0 = blockIdx.y * 32;
    int tx = threadIdx.x, ty = threadIdx.y;
#pragma unroll
    for (int j = 0; j < 32; j += 8)
        tile[ty + j][tx] = s[(size_t)(c0 + ty + j) * NU + n0 + tx];
    __syncthreads();
#pragma unroll
    for (int j = 0; j < 32; j += 8)
        d[(size_t)(n0 + ty + j) * CIN + C2 + c0 + tx] = tile[tx][ty + j];
}

// ---------------- K4/K5: fused conv + BN + ReLU GEMM
// LAYER 1: C = W1(256x512) * FT^T  (B operand (n,k) row-major, "NT"), out g_h1
// LAYER 2: C = W2(256x256) * h1    (B operand (k,n) row-major, "NN"), out g_h
template <int LAYER>
__global__ void __launch_bounds__(256) k_gemm(const float* __restrict__ Wm) {
    constexpr int Ktot = (LAYER == 1) ? 512 : 256;
    __shared__ float As[16][128];
    __shared__ float Bs[16][64];
    int b = blockIdx.z;
    const float* Bmat = (LAYER == 1) ? (g_FT + (size_t)b * NU * CIN)
                                     : (g_h1 + (size_t)b * DD * NU);
    float* Out = (LAYER == 1) ? (g_h1 + (size_t)b * DD * NU)
                              : (g_h + (size_t)b * DD * NU);
    const float* alpha = (LAYER == 1) ? g_alpha1 : g_alpha2;
    const float* beta  = (LAYER == 1) ? g_beta1  : g_beta2;

    int m0 = blockIdx.y * 128;
    int n0 = blockIdx.x * 64;
    int t = threadIdx.x;
    int tm = t >> 4;            // 0..15 -> 8 m-rows each
    int tn = t & 15;            // 0..15 -> 4 n-cols each
    int lr = t >> 2;            // 0..63
    int lk = (t & 3) * 4;       // 0,4,8,12

    float acc[8][4];
#pragma unroll
    for (int i = 0; i < 8; i++)
#pragma unroll
        for (int j = 0; j < 4; j++) acc[i][j] = 0.f;

    for (int k0 = 0; k0 < Ktot; k0 += 16) {
        // A tile 128x16 (k-contiguous rows)
#pragma unroll
        for (int h = 0; h < 2; h++) {
            int row = lr + 64 * h;
            float4 v = *(const float4*)(Wm + (size_t)(m0 + row) * Ktot + k0 + lk);
            As[lk + 0][row] = v.x; As[lk + 1][row] = v.y;
            As[lk + 2][row] = v.z; As[lk + 3][row] = v.w;
        }
        // B tile
        if (LAYER == 1) {  // NT: Bmat is (N, Ktot)
            float4 v = *(const float4*)(Bmat + (size_t)(n0 + lr) * Ktot + k0 + lk);
            Bs[lk + 0][lr] = v.x; Bs[lk + 1][lr] = v.y;
            Bs[lk + 2][lr] = v.z; Bs[lk + 3][lr] = v.w;
        } else {           // NN: Bmat is (Ktot, N)
            int kr = t >> 4;
            int nc = (t & 15) * 4;
            float4 v = *(const float4*)(Bmat + (size_t)(k0 + kr) * NU + n0 + nc);
            *(float4*)(&Bs[kr][nc]) = v;
        }
        __syncthreads();
#pragma unroll
        for (int kk = 0; kk < 16; kk++) {
            float4 a0 = *(const float4*)(&As[kk][tm * 8]);
            float4 a1 = *(const float4*)(&As[kk][tm * 8 + 4]);
            float4 b4 = *(const float4*)(&Bs[kk][tn * 4]);
            float av[8] = {a0.x, a0.y, a0.z, a0.w, a1.x, a1.y, a1.z, a1.w};
            float bv[4] = {b4.x, b4.y, b4.z, b4.w};
#pragma unroll
            for (int i = 0; i < 8; i++)
#pragma unroll
                for (int j = 0; j < 4; j++)
                    acc[i][j] = fmaf(av[i], bv[j], acc[i][j]);
        }
        __syncthreads();
    }
#pragma unroll
    for (int i = 0; i < 8; i++) {
        int o = m0 + tm * 8 + i;
        float s = alpha[o], sh = beta[o];
        float4 v;
        v.x = fmaxf(acc[i][0] * s + sh, 0.f);
        v.y = fmaxf(acc[i][1] * s + sh, 0.f);
        v.z = fmaxf(acc[i][2] * s + sh, 0.f);
        v.w = fmaxf(acc[i][3] * s + sh, 0.f);
        *(float4*)(Out + (size_t)o * NU + n0 + tn * 4) = v;
    }
}

// ---------------- K6: soft assignment A = softmax_k(scale_k * ||x - c_k||^2), plus Asum
__global__ void __launch_bounds__(256) k_assign(const float* __restrict__ cw,
                                                const float* __restrict__ scale) {
    __shared__ float cws[256 * 40];   // [d][k], row pad 40 (16B aligned rows)
    __shared__ float wsum[8][KE];
    int b = blockIdx.y;
    int t = threadIdx.x;
    int n = blockIdx.x * 256 + t;
    for (int e = t; e < KE * DD; e += 256) {
        int k = e >> 8, d = e & 255;
        cws[d * 40 + k] = cw[e];
    }
    __syncthreads();

    const float* hb = g_h + (size_t)b * DD * NU + n;
    float dot[KE];
#pragma unroll
    for (int k = 0; k < KE; k++) dot[k] = 0.f;
    float xn2 = 0.f;
#pragma unroll 4
    for (int d = 0; d < DD; d++) {
        float xv = hb[(size_t)d * NU];
        xn2 += xv * xv;
        const float4* row = (const float4*)(cws + d * 40);
#pragma unroll
        for (int k4 = 0; k4 < 8; k4++) {
            float4 c4 = row[k4];
            dot[k4 * 4 + 0] += xv * c4.x;
            dot[k4 * 4 + 1] += xv * c4.y;
            dot[k4 * 4 + 2] += xv * c4.z;
            dot[k4 * 4 + 3] += xv * c4.w;
        }
    }
    float sl[KE];
    float mx = -1e30f;
#pragma unroll
    for (int k = 0; k < KE; k++) {
        sl[k] = scale[k] * (xn2 - 2.f * dot[k] + g_c2[k]);
        mx = fmaxf(mx, sl[k]);
    }
    float se = 0.f;
#pragma unroll
    for (int k = 0; k < KE; k++) { sl[k] = expf(sl[k] - mx); se += sl[k]; }
    float inv = 1.f / se;
#pragma unroll
    for (int k = 0; k < KE; k++) sl[k] *= inv;

    float* Ab = g_A + ((size_t)b * NU + n) * KE;
#pragma unroll
    for (int k = 0; k < KE; k += 4) {
        float4 v = {sl[k], sl[k + 1], sl[k + 2], sl[k + 3]};
        *(float4*)(Ab + k) = v;
    }
    // block-level Asum reduction
    int lane = t & 31, w = t >> 5;
#pragma unroll
    for (int k = 0; k < KE; k++) {
        float v = sl[k];
        v += __shfl_xor_sync(0xffffffff, v, 16);
        v += __shfl_xor_sync(0xffffffff, v, 8);
        v += __shfl_xor_sync(0xffffffff, v, 4);
        v += __shfl_xor_sync(0xffffffff, v, 2);
        v += __shfl_xor_sync(0xffffffff, v, 1);
        if (lane == 0) wsum[w][k] = v;
    }
    __syncthreads();
    if (t < KE) {
        float s = 0.f;
#pragma unroll
        for (int w2 = 0; w2 < 8; w2++) s += wsum[w2][t];
        atomicAdd(&g_Asum[b * KE + t], s);
    }
}

// ---------------- K7: E[b,k,d] = sum_n A[b,n,k]*h[b,d,n] - Asum*cw, relu, accumulate ||E||^2
__global__ void __launch_bounds__(256) k_egemm(const float* __restrict__ cw) {
    __shared__ float hs[64][64];
    __shared__ float As_[64][KE];
    __shared__ float red[256];
    int b = blockIdx.y;
    int d0 = blockIdx.x * 64;
    int t = threadIdx.x;
    int kq = t & 7;     // k = kq*4 .. +3
    int dq = t >> 3;    // d = d0 + dq*2 .. +1
    float acc[2][4] = {};
    const float* hb = g_h + (size_t)b * DD * NU;
    const float* Ab = g_A + (size_t)b * NU * KE;

    for (int n0 = 0; n0 < NU; n0 += 64) {
#pragma unroll
        for (int r = 0; r < 16; r++) {
            int e = r * 256 + t;
            int dd = e >> 6, nn = e & 63;
            hs[dd][nn] = hb[(size_t)(d0 + dd) * NU + n0 + nn];
        }
#pragma unroll
        for (int r = 0; r < 8; r++) {
            int e = r * 256 + t;
            As_[e >> 5][e & 31] = Ab[(size_t)n0 * KE + e];
        }
        __syncthreads();
#pragma unroll 4
        for (int nn = 0; nn < 64; nn++) {
            float h0 = hs[dq * 2 + 0][nn];
            float h1 = hs[dq * 2 + 1][nn];
            float a0 = As_[nn][kq * 4 + 0];
            float a1 = As_[nn][kq * 4 + 1];
            float a2 = As_[nn][kq * 4 + 2];
            float a3 = As_[nn][kq * 4 + 3];
            acc[0][0] += h0 * a0; acc[0][1] += h0 * a1;
            acc[0][2] += h0 * a2; acc[0][3] += h0 * a3;
            acc[1][0] += h1 * a0; acc[1][1] += h1 * a1;
            acc[1][2] += h1 * a2; acc[1][3] += h1 * a3;
        }
        __syncthreads();
    }
    float lsum = 0.f;
#pragma unroll
    for (int i = 0; i < 2; i++) {
        int d = d0 + dq * 2 + i;
#pragma unroll
        for (int j = 0; j < 4; j++) {
            int k = kq * 4 + j;
            float e = acc[i][j] - g_Asum[b * KE + k] * cw[k * DD + d];
            e = fmaxf(e, 0.f);
            g_E[((size_t)b * KE + k) * DD + d] = e;
            lsum += e * e;
        }
    }
    red[t] = lsum;
    __syncthreads();
    for (int s = 128; s > 0; s >>= 1) {
        if (t < s) red[t] += red[t + s];
        __syncthreads();
    }
    if (t == 0) atomicAdd(&g_normsq[b], red[0]);
}

// ---------------- K8: ctx[b,j] = sigmoid(dot(E_normalized[b], lin_w[j]) + lin_b[j])
__global__ void __launch_bounds__(256) k_ctx(const float* __restrict__ lw,
                                             const float* __restrict__ lb) {
    __shared__ float red[256];
    int b = blockIdx.y, j = blockIdx.x, t = threadIdx.x;
    const float4* e = (const float4*)(g_E + (size_t)b * KE * DD);
    const float4* w = (const float4*)(lw + (size_t)j * KE * DD);
    float s = 0.f;
#pragma unroll
    for (int i = 0; i < 8; i++) {
        int p = t + i * 256;
        float4 ev = e[p], wv = w[p];
        s += ev.x * wv.x + ev.y * wv.y + ev.z * wv.z + ev.w * wv.w;
    }
    red[t] = s;
    __syncthreads();
    for (int st = 128; st > 0; st >>= 1) {
        if (t < st) red[t] += red[t + st];
        __syncthreads();
    }
    if (t == 0) {
        float norm = fmaxf(sqrtf(g_normsq[b]), 1e-12f);
        float v = red[0] / norm + lb[j];
        g_ctx[b * DD + j] = 1.f / (1.f + expf(-v));
    }
}

// ---------------- K9: out[b,d,n] = h[b,d,n] * ctx[b,d]
__global__ void __launch_bounds__(256) k_out(float* __restrict__ out) {
    size_t i = (size_t)blockIdx.x * 256 + threadIdx.x;  // float4 index
    float4 h4 = ((const float4*)g_h)[i];
    size_t fi = i * 4;
    int d = (int)((fi >> 13) & 255);
    int b = (int)(fi >> 21);
    float c = g_ctx[b * DD + d];
    float4 v = {h4.x * c, h4.y * c, h4.z * c, h4.w * c};
    ((float4*)out)[i] = v;
}

// ---------------- launch --------------------------------------------------
extern "C" void kernel_launch(void* const* d_in, const int* in_sizes, int n_in,
                              void* d_out, int out_size) {
    const float* unknown = (const float*)d_in[0];
    const float* known   = (const float*)d_in[1];
    const float* uf      = (const float*)d_in[2];
    const float* kf      = (const float*)d_in[3];
    const float* w1      = (const float*)d_in[4];
    const float* cb1     = (const float*)d_in[5];
    const float* bg1     = (const float*)d_in[6];
    const float* bb1     = (const float*)d_in[7];
    const float* bm1     = (const float*)d_in[8];
    const float* bv1     = (const float*)d_in[9];
    const float* w2      = (const float*)d_in[10];
    const float* cb2     = (const float*)d_in[11];
    const float* bg2     = (const float*)d_in[12];
    const float* bb2     = (const float*)d_in[13];
    const float* bm2     = (const float*)d_in[14];
    const float* bv2     = (const float*)d_in[15];
    const float* cw      = (const float*)d_in[16];
    const float* esc     = (const float*)d_in[17];
    const float* lw      = (const float*)d_in[18];
    const float* lb      = (const float*)d_in[19];
    float* out = (float*)d_out;

    k_params<<<1, 256>>>(cb1, bg1, bb1, bm1, bv1, cb2, bg2, bb2, bm2, bv2, cw);
    k_transpose_kf<<<dim3(MK / 32, C2 / 32, Bsz), dim3(32, 8)>>>(kf);
    k_three_nn<<<dim3(NU / 256, Bsz), 256>>>(unknown, known);
    k_interp<<<dim3(NU / 4, Bsz), 256>>>();
    k_uf_to_FT<<<dim3(NU / 32, C1 / 32, Bsz), dim3(32, 8)>>>(uf);
    k_gemm<1><<<dim3(NU / 64, 2, Bsz), 256>>>(w1);
    k_gemm<2><<<dim3(NU / 64, 2, Bsz), 256>>>(w2);
    k_assign<<<dim3(NU / 256, Bsz), 256>>>(cw, esc);
    k_egemm<<<dim3(DD / 64, Bsz), 256>>>(cw);
    k_ctx<<<dim3(DD, Bsz), 256>>>(lw, lb);
    k_out<<<(Bsz * DD * NU) / 4 / 256, 256>>>(out);
}